// round 3
// baseline (speedup 1.0000x reference)
#include <cuda_runtime.h>
#include <cuda_bf16.h>

#define N_NODES 100000
#define N_EDGES 1000000
#define D_FEAT  64
#define MAXD    96

// Adjacency buckets. g_cnt zero-initialized at load; k_gin resets it to zero
// after consuming, so every replay of the captured graph sees the same state.
__device__ int g_cnt[N_NODES];
__device__ int g_adj[(size_t)N_NODES * MAXD];

// ---------------------------------------------------------------------------
// Fill: bucket both directions of each edge.
// ---------------------------------------------------------------------------
__global__ void k_fill(const int* __restrict__ ref_a, const int* __restrict__ ref_b) {
    int e = blockIdx.x * blockDim.x + threadIdx.x;
    if (e >= N_EDGES) return;
    int a = __ldg(&ref_a[e]);
    int b = __ldg(&ref_b[e]);
    int pa = atomicAdd(&g_cnt[a], 1);
    if (pa < MAXD) g_adj[(size_t)a * MAXD + pa] = b;
    int pb = atomicAdd(&g_cnt[b], 1);
    if (pb < MAXD) g_adj[(size_t)b * MAXD + pb] = a;
}

// ---------------------------------------------------------------------------
// Fused gather + 2-layer TF32 MLP.
//   out = relu(relu((X[v] + sum_nbr X[u]) @ Wh + bh) @ Wo + bo)
// 256 threads = 8 warps; warp owns 16 rows (m16n8k8 tiles, 8 n-tiles).
// A fragments live entirely in registers via the k-permutation trick:
//   layer-1: phys col 16t+j  <-> logical k = t+4j   (thread tig owns its quarter)
//   layer-2: accumulator slots ARE the next A fragment (W2 rows permuted).
// Weights staged in smem pre-packed in fragment order -> one LDS.64 per (s,nt).
// ---------------------------------------------------------------------------
__device__ __forceinline__ unsigned f2tf32(float f) {
    unsigned u;
    asm("cvt.rna.tf32.f32 %0, %1;" : "=r"(u) : "f"(f));
    return u;
}

__device__ __forceinline__ void mma_tf32(float* d, unsigned a0, unsigned a1,
                                         unsigned a2, unsigned a3,
                                         unsigned b0, unsigned b1) {
    asm volatile(
        "mma.sync.aligned.m16n8k8.row.col.f32.tf32.tf32.f32 "
        "{%0,%1,%2,%3}, {%4,%5,%6,%7}, {%8,%9}, {%0,%1,%2,%3};\n"
        : "+f"(d[0]), "+f"(d[1]), "+f"(d[2]), "+f"(d[3])
        : "r"(a0), "r"(a1), "r"(a2), "r"(a3), "r"(b0), "r"(b1));
}

__global__ __launch_bounds__(256)
void k_gin(const float4* __restrict__ X4,
           const float* __restrict__ Wh_g, const float* __restrict__ bh,
           const float* __restrict__ Wo_g, const float* __restrict__ bo,
           float* __restrict__ out) {
    // Packed weight fragments: Wp[layer][((s*8+nt)*32 + lane)*2 + {0,1}]
    __shared__ unsigned Wp[2][4096];

    const int tid  = threadIdx.x;
    const int lane = tid & 31;
    const int warp = tid >> 5;
    const int g    = lane >> 2;      // 0..7
    const int tg   = lane & 3;       // 0..3

    // ---- Stage weights in fragment-packed order ----
    #pragma unroll
    for (int l = 0; l < 2; l++) {
        const float* W = l ? Wo_g : Wh_g;
        #pragma unroll
        for (int ii = 0; ii < 8; ii++) {
            int i = tid + ii * 256;          // 0..2047
            int ln = i & 31;
            int nt = (i >> 5) & 7;
            int s  = i >> 8;                 // 0..7
            int tgg = ln & 3, gg = ln >> 2;
            // layer 1: fragment k-slot 8s+tgg holds TRUE row 16*tgg + 2s
            // layer 2: fragment k-slot 8s+tgg holds TRUE row 8s + 2*tgg
            int r0 = l ? (8 * s + 2 * tgg) : (16 * tgg + 2 * s);
            int n  = nt * 8 + gg;
            Wp[l][2 * i]     = f2tf32(__ldg(&W[r0 * 64 + n]));
            Wp[l][2 * i + 1] = f2tf32(__ldg(&W[(r0 + 1) * 64 + n]));
        }
    }
    __syncthreads();

    const int rowbase = blockIdx.x * 128 + warp * 16;
    const int r0 = rowbase + g;          // fragment rows g
    const int r1 = rowbase + g + 8;      // fragment rows g+8
    const bool v0 = r0 < N_NODES;
    const bool v1 = r1 < N_NODES;

    // ---- Gather: s0/s1 accumulate (X[self] + sum of neighbor rows),
    //      thread owns physical cols [16*tg, 16*tg+16) of its two rows.
    float4 s0[4], s1[4];
    const float4* xq;
    #pragma unroll
    for (int q = 0; q < 4; q++) {
        s0[q] = make_float4(0.f, 0.f, 0.f, 0.f);
        s1[q] = make_float4(0.f, 0.f, 0.f, 0.f);
    }
    if (v0) {
        xq = X4 + (size_t)r0 * 16 + tg * 4;
        #pragma unroll
        for (int q = 0; q < 4; q++) s0[q] = __ldg(&xq[q]);
    }
    if (v1) {
        xq = X4 + (size_t)r1 * 16 + tg * 4;
        #pragma unroll
        for (int q = 0; q < 4; q++) s1[q] = __ldg(&xq[q]);
    }

    int d0 = v0 ? min(g_cnt[r0], MAXD) : 0;
    int d1 = v1 ? min(g_cnt[r1], MAXD) : 0;
    // reset for next replay (read of d happened in program order above)
    if (v0 && tg == 0) g_cnt[r0] = 0;
    if (v1 && tg == 0) g_cnt[r1] = 0;

    for (int i = 0; i < d0; i++) {
        int u = __ldg(&g_adj[(size_t)r0 * MAXD + i]);
        xq = X4 + (size_t)u * 16 + tg * 4;
        float4 x0 = __ldg(&xq[0]), x1 = __ldg(&xq[1]);
        float4 x2 = __ldg(&xq[2]), x3 = __ldg(&xq[3]);
        s0[0].x += x0.x; s0[0].y += x0.y; s0[0].z += x0.z; s0[0].w += x0.w;
        s0[1].x += x1.x; s0[1].y += x1.y; s0[1].z += x1.z; s0[1].w += x1.w;
        s0[2].x += x2.x; s0[2].y += x2.y; s0[2].z += x2.z; s0[2].w += x2.w;
        s0[3].x += x3.x; s0[3].y += x3.y; s0[3].z += x3.z; s0[3].w += x3.w;
    }
    for (int i = 0; i < d1; i++) {
        int u = __ldg(&g_adj[(size_t)r1 * MAXD + i]);
        xq = X4 + (size_t)u * 16 + tg * 4;
        float4 x0 = __ldg(&xq[0]), x1 = __ldg(&xq[1]);
        float4 x2 = __ldg(&xq[2]), x3 = __ldg(&xq[3]);
        s1[0].x += x0.x; s1[0].y += x0.y; s1[0].z += x0.z; s1[0].w += x0.w;
        s1[1].x += x1.x; s1[1].y += x1.y; s1[1].z += x1.z; s1[1].w += x1.w;
        s1[2].x += x2.x; s1[2].y += x2.y; s1[2].z += x2.z; s1[2].w += x2.w;
        s1[3].x += x3.x; s1[3].y += x3.y; s1[3].z += x3.z; s1[3].w += x3.w;
    }

    // ---- Convert to TF32 A fragments (a?r[j] = row, phys col 16*tg + j) ----
    unsigned a0r[16], a1r[16];
    #pragma unroll
    for (int q = 0; q < 4; q++) {
        a0r[4 * q + 0] = f2tf32(s0[q].x); a0r[4 * q + 1] = f2tf32(s0[q].y);
        a0r[4 * q + 2] = f2tf32(s0[q].z); a0r[4 * q + 3] = f2tf32(s0[q].w);
        a1r[4 * q + 0] = f2tf32(s1[q].x); a1r[4 * q + 1] = f2tf32(s1[q].y);
        a1r[4 * q + 2] = f2tf32(s1[q].z); a1r[4 * q + 3] = f2tf32(s1[q].w);
    }

    // ================= Layer 1 =================
    float acc[8][4];
    #pragma unroll
    for (int nt = 0; nt < 8; nt++) {
        float blo = __ldg(&bh[nt * 8 + 2 * tg]);
        float bhi = __ldg(&bh[nt * 8 + 2 * tg + 1]);
        acc[nt][0] = blo; acc[nt][1] = bhi; acc[nt][2] = blo; acc[nt][3] = bhi;
    }
    #pragma unroll
    for (int s = 0; s < 8; s++) {
        unsigned A0 = a0r[2 * s], A2 = a0r[2 * s + 1];
        unsigned A1 = a1r[2 * s], A3 = a1r[2 * s + 1];
        #pragma unroll
        for (int nt = 0; nt < 8; nt++) {
            uint2 b = *(const uint2*)&Wp[0][((s * 8 + nt) * 32 + lane) * 2];
            mma_tf32(acc[nt], A0, A1, A2, A3, b.x, b.y);
        }
    }

    // ---- relu + cvt: accumulators become layer-2 A fragments directly ----
    unsigned h0[8], h1[8], h2[8], h3[8];   // per s2: a0,a1,a2,a3
    #pragma unroll
    for (int s = 0; s < 8; s++) {
        h0[s] = f2tf32(fmaxf(acc[s][0], 0.f));   // row g,  col 8s+2tg
        h1[s] = f2tf32(fmaxf(acc[s][2], 0.f));   // row g+8,col 8s+2tg
        h2[s] = f2tf32(fmaxf(acc[s][1], 0.f));   // row g,  col 8s+2tg+1
        h3[s] = f2tf32(fmaxf(acc[s][3], 0.f));   // row g+8,col 8s+2tg+1
    }

    // ================= Layer 2 =================
    #pragma unroll
    for (int nt = 0; nt < 8; nt++) {
        float blo = __ldg(&bo[nt * 8 + 2 * tg]);
        float bhi = __ldg(&bo[nt * 8 + 2 * tg + 1]);
        acc[nt][0] = blo; acc[nt][1] = bhi; acc[nt][2] = blo; acc[nt][3] = bhi;
    }
    #pragma unroll
    for (int s = 0; s < 8; s++) {
        #pragma unroll
        for (int nt = 0; nt < 8; nt++) {
            uint2 b = *(const uint2*)&Wp[1][((s * 8 + nt) * 32 + lane) * 2];
            mma_tf32(acc[nt], h0[s], h1[s], h2[s], h3[s], b.x, b.y);
        }
    }

    // ---- Epilogue: relu + direct STG.64 (cols 8nt+2tg are 8B aligned) ----
    #pragma unroll
    for (int nt = 0; nt < 8; nt++) {
        if (v0) {
            float2 v = make_float2(fmaxf(acc[nt][0], 0.f), fmaxf(acc[nt][1], 0.f));
            *(float2*)&out[(size_t)r0 * 64 + nt * 8 + 2 * tg] = v;
        }
        if (v1) {
            float2 v = make_float2(fmaxf(acc[nt][2], 0.f), fmaxf(acc[nt][3], 0.f));
            *(float2*)&out[(size_t)r1 * 64 + nt * 8 + 2 * tg] = v;
        }
    }
}

// ---------------------------------------------------------------------------
// Inputs: 0=X, 1=ref_a, 2=ref_b, 3=v_map(unused), 4=v_count(unused),
//         5=W_hidden, 6=b_hidden, 7=W_out, 8=b_out
// ---------------------------------------------------------------------------
extern "C" void kernel_launch(void* const* d_in, const int* in_sizes, int n_in,
                              void* d_out, int out_size) {
    const float* X   = (const float*)d_in[0];
    const int* ref_a = (const int*)d_in[1];
    const int* ref_b = (const int*)d_in[2];
    const float* Wh  = (const float*)d_in[5];
    const float* bh  = (const float*)d_in[6];
    const float* Wo  = (const float*)d_in[7];
    const float* bo  = (const float*)d_in[8];
    float* out = (float*)d_out;

    // 1) bucket adjacency (g_cnt zero-invariant maintained by k_gin)
    k_fill<<<(N_EDGES + 255) / 256, 256>>>(ref_a, ref_b);

    // 2) fused gather + MLP
    int blocks = (N_NODES + 127) / 128;   // 782
    k_gin<<<blocks, 256>>>((const float4*)X, Wh, bh, Wo, bo, out);
}

// round 4
// speedup vs baseline: 1.0948x; 1.0948x over previous
#include <cuda_runtime.h>
#include <cuda_bf16.h>

#define N_NODES 100000
#define N_EDGES 1000000
#define D_FEAT  64

// Neighbor-sum accumulator. Zero-initialized at module load; k_mlp re-zeroes
// its tile after consuming, so every graph replay sees zeros (deterministic).
__device__ float g_agg[N_NODES * D_FEAT];

// ---------------------------------------------------------------------------
// Edge scatter: 16 threads per edge, one float4 chunk each, both directions.
// Coalesced 256B row reads and 256B RED bursts; at the LTS throughput floor.
// ---------------------------------------------------------------------------
__device__ __forceinline__ void red_add_v4(float* addr, float4 v) {
    asm volatile("red.global.add.v4.f32 [%0], {%1, %2, %3, %4};"
                 :: "l"(addr), "f"(v.x), "f"(v.y), "f"(v.z), "f"(v.w)
                 : "memory");
}

__global__ void k_scatter(const float4* __restrict__ X4,
                          const int* __restrict__ ref_a,
                          const int* __restrict__ ref_b) {
    unsigned t = blockIdx.x * blockDim.x + threadIdx.x;
    unsigned e = t >> 4;
    unsigned c = t & 15;
    if (e >= N_EDGES) return;
    int a = __ldg(&ref_a[e]);
    int b = __ldg(&ref_b[e]);
    const int F4 = D_FEAT / 4;   // 16
    float4 xb = __ldg(&X4[(size_t)b * F4 + c]);
    float4 xa = __ldg(&X4[(size_t)a * F4 + c]);
    red_add_v4(&g_agg[((size_t)a * F4 + c) * 4], xb);
    red_add_v4(&g_agg[((size_t)b * F4 + c) * 4], xa);
}

// ---------------------------------------------------------------------------
// Register-fragment TF32 MLP:  out = relu(relu((X+agg) @ Wh + bh) @ Wo + bo)
// 256 threads = 8 warps; each warp owns 16 rows (m16n8k8, 8 n-tiles).
// A fragments live entirely in registers via the k-permutation trick:
//   layer-1: phys col 16t+j <-> logical k = t+4j (thread tg owns its quarter)
//   layer-2: layer-1 accumulators ARE the next A fragment (W2 rows permuted).
// Weights staged in smem pre-packed in fragment order -> one LDS.64 per (s,nt).
// Also re-zeroes the block's agg tile (coalesced) for graph-replay invariance.
// ---------------------------------------------------------------------------
__device__ __forceinline__ unsigned f2tf32(float f) {
    unsigned u;
    asm("cvt.rna.tf32.f32 %0, %1;" : "=r"(u) : "f"(f));
    return u;
}

__device__ __forceinline__ void mma_tf32(float* d, unsigned a0, unsigned a1,
                                         unsigned a2, unsigned a3,
                                         unsigned b0, unsigned b1) {
    asm volatile(
        "mma.sync.aligned.m16n8k8.row.col.f32.tf32.tf32.f32 "
        "{%0,%1,%2,%3}, {%4,%5,%6,%7}, {%8,%9}, {%0,%1,%2,%3};\n"
        : "+f"(d[0]), "+f"(d[1]), "+f"(d[2]), "+f"(d[3])
        : "r"(a0), "r"(a1), "r"(a2), "r"(a3), "r"(b0), "r"(b1));
}

__global__ __launch_bounds__(256)
void k_mlp(const float4* __restrict__ agg4, const float4* __restrict__ X4,
           const float* __restrict__ Wh_g, const float* __restrict__ bh,
           const float* __restrict__ Wo_g, const float* __restrict__ bo,
           float* __restrict__ out, float4* __restrict__ aggz) {
    // Packed weight fragments: Wp[layer][((s*8+nt)*32 + lane)*2 + {0,1}]
    __shared__ unsigned Wp[2][4096];

    const int tid  = threadIdx.x;
    const int lane = tid & 31;
    const int warp = tid >> 5;
    const int g    = lane >> 2;      // 0..7
    const int tg   = lane & 3;       // 0..3
    const int row0 = blockIdx.x * 128;

    // ---- Stage weights in fragment-packed order ----
    #pragma unroll
    for (int l = 0; l < 2; l++) {
        const float* W = l ? Wo_g : Wh_g;
        #pragma unroll
        for (int ii = 0; ii < 8; ii++) {
            int i = tid + ii * 256;          // 0..2047
            int ln = i & 31;
            int nt = (i >> 5) & 7;
            int s  = i >> 8;                 // 0..7
            int tgg = ln & 3, gg = ln >> 2;
            // layer 1: fragment k-slot 8s+tgg holds TRUE row 16*tgg + 2s
            // layer 2: fragment k-slot 8s+tgg holds TRUE row 8s + 2*tgg
            int r = l ? (8 * s + 2 * tgg) : (16 * tgg + 2 * s);
            int n = nt * 8 + gg;
            Wp[l][2 * i]     = f2tf32(__ldg(&W[r * 64 + n]));
            Wp[l][2 * i + 1] = f2tf32(__ldg(&W[(r + 1) * 64 + n]));
        }
    }

    const int r0 = row0 + warp * 16 + g;       // fragment rows g
    const int r1 = r0 + 8;                     // fragment rows g+8
    const bool v0 = r0 < N_NODES;
    const bool v1 = r1 < N_NODES;

    // ---- Load A = X + agg directly into fragment registers ----
    unsigned a0r[16], a1r[16];    // [j] = row r0/r1, phys col 16*tg + j
    #pragma unroll
    for (int q = 0; q < 4; q++) {
        float4 s0 = make_float4(0.f, 0.f, 0.f, 0.f);
        float4 s1 = make_float4(0.f, 0.f, 0.f, 0.f);
        if (v0) {
            float4 a = __ldg(&agg4[(size_t)r0 * 16 + tg * 4 + q]);
            float4 x = __ldg(&X4[(size_t)r0 * 16 + tg * 4 + q]);
            s0 = make_float4(a.x + x.x, a.y + x.y, a.z + x.z, a.w + x.w);
        }
        if (v1) {
            float4 a = __ldg(&agg4[(size_t)r1 * 16 + tg * 4 + q]);
            float4 x = __ldg(&X4[(size_t)r1 * 16 + tg * 4 + q]);
            s1 = make_float4(a.x + x.x, a.y + x.y, a.z + x.z, a.w + x.w);
        }
        a0r[4 * q + 0] = f2tf32(s0.x); a0r[4 * q + 1] = f2tf32(s0.y);
        a0r[4 * q + 2] = f2tf32(s0.z); a0r[4 * q + 3] = f2tf32(s0.w);
        a1r[4 * q + 0] = f2tf32(s1.x); a1r[4 * q + 1] = f2tf32(s1.y);
        a1r[4 * q + 2] = f2tf32(s1.z); a1r[4 * q + 3] = f2tf32(s1.w);
    }

    // All agg reads in this block are consumed above (values in registers);
    // barrier orders them against the zero-stores below (intra-block tile).
    __syncthreads();

    // ---- Re-zero this block's agg tile, fully coalesced ----
    {
        const float4 z4 = make_float4(0.f, 0.f, 0.f, 0.f);
        #pragma unroll
        for (int i = 0; i < 8; i++) {
            int idx = tid + i * 256;          // 0..2047 float4 within tile
            int grow = row0 + (idx >> 4);
            if (grow < N_NODES)
                aggz[(size_t)grow * 16 + (idx & 15)] = z4;
        }
    }

    // ================= Layer 1 =================
    float acc[8][4];
    #pragma unroll
    for (int nt = 0; nt < 8; nt++) {
        float blo = __ldg(&bh[nt * 8 + 2 * tg]);
        float bhi = __ldg(&bh[nt * 8 + 2 * tg + 1]);
        acc[nt][0] = blo; acc[nt][1] = bhi; acc[nt][2] = blo; acc[nt][3] = bhi;
    }
    #pragma unroll
    for (int s = 0; s < 8; s++) {
        unsigned A0 = a0r[2 * s], A2 = a0r[2 * s + 1];
        unsigned A1 = a1r[2 * s], A3 = a1r[2 * s + 1];
        #pragma unroll
        for (int nt = 0; nt < 8; nt++) {
            uint2 b = *(const uint2*)&Wp[0][((s * 8 + nt) * 32 + lane) * 2];
            mma_tf32(acc[nt], A0, A1, A2, A3, b.x, b.y);
        }
    }

    // ---- relu + cvt: accumulators become layer-2 A fragments directly ----
    unsigned h0[8], h1[8], h2[8], h3[8];
    #pragma unroll
    for (int s = 0; s < 8; s++) {
        h0[s] = f2tf32(fmaxf(acc[s][0], 0.f));   // row g,   col 8s+2tg
        h1[s] = f2tf32(fmaxf(acc[s][2], 0.f));   // row g+8, col 8s+2tg
        h2[s] = f2tf32(fmaxf(acc[s][1], 0.f));   // row g,   col 8s+2tg+1
        h3[s] = f2tf32(fmaxf(acc[s][3], 0.f));   // row g+8, col 8s+2tg+1
    }

    // ================= Layer 2 =================
    #pragma unroll
    for (int nt = 0; nt < 8; nt++) {
        float blo = __ldg(&bo[nt * 8 + 2 * tg]);
        float bhi = __ldg(&bo[nt * 8 + 2 * tg + 1]);
        acc[nt][0] = blo; acc[nt][1] = bhi; acc[nt][2] = blo; acc[nt][3] = bhi;
    }
    #pragma unroll
    for (int s = 0; s < 8; s++) {
        #pragma unroll
        for (int nt = 0; nt < 8; nt++) {
            uint2 b = *(const uint2*)&Wp[1][((s * 8 + nt) * 32 + lane) * 2];
            mma_tf32(acc[nt], h0[s], h1[s], h2[s], h3[s], b.x, b.y);
        }
    }

    // ---- Epilogue: relu + direct STG.64 ----
    #pragma unroll
    for (int nt = 0; nt < 8; nt++) {
        if (v0) {
            float2 v = make_float2(fmaxf(acc[nt][0], 0.f), fmaxf(acc[nt][1], 0.f));
            *(float2*)&out[(size_t)r0 * 64 + nt * 8 + 2 * tg] = v;
        }
        if (v1) {
            float2 v = make_float2(fmaxf(acc[nt][2], 0.f), fmaxf(acc[nt][3], 0.f));
            *(float2*)&out[(size_t)r1 * 64 + nt * 8 + 2 * tg] = v;
        }
    }
}

// ---------------------------------------------------------------------------
// Inputs: 0=X, 1=ref_a, 2=ref_b, 3=v_map(unused), 4=v_count(unused),
//         5=W_hidden, 6=b_hidden, 7=W_out, 8=b_out
// ---------------------------------------------------------------------------
extern "C" void kernel_launch(void* const* d_in, const int* in_sizes, int n_in,
                              void* d_out, int out_size) {
    const float* X   = (const float*)d_in[0];
    const int* ref_a = (const int*)d_in[1];
    const int* ref_b = (const int*)d_in[2];
    const float* Wh  = (const float*)d_in[5];
    const float* bh  = (const float*)d_in[6];
    const float* Wo  = (const float*)d_in[7];
    const float* bo  = (const float*)d_in[8];
    float* out = (float*)d_out;

    float* agg;
    cudaGetSymbolAddress((void**)&agg, g_agg);

    // 1) edge scatter into zeroed agg (zero-invariant maintained by k_mlp)
    {
        long long total = (long long)N_EDGES * 16;
        int blocks = (int)((total + 255) / 256);
        k_scatter<<<blocks, 256>>>((const float4*)X, ref_a, ref_b);
    }

    // 2) register-fragment TF32 MLP (adds X, consumes agg, re-zeroes agg)
    {
        int blocks = (N_NODES + 127) / 128;   // 782
        k_mlp<<<blocks, 256>>>((const float4*)agg, (const float4*)X,
                               Wh, bh, Wo, bo, out, (float4*)agg);
    }
}